// round 7
// baseline (speedup 1.0000x reference)
#include <cuda_runtime.h>
#include <cstdint>

#define TT 512
#define BB 64
#define II 1024
#define HH 1024
#define UPITCH 1026   // padded smem pitch (floats) for rnn

// h3 exchange buffer, [parity][h-index][b]
__device__ float g_h3[2][HH][BB];
// row-scoped barrier state: 4 rows, padded 128B apart; self-resetting
__device__ unsigned int g_cnt4[4 * 32];
__device__ unsigned int g_ack4[4 * 32];
__device__ volatile unsigned int g_flag4[4 * 32];

__device__ __forceinline__ unsigned long long pk2(float lo, float hi) {
    unsigned long long r;
    asm("mov.b64 %0, {%1, %2};" : "=l"(r) : "f"(lo), "f"(hi));
    return r;
}
__device__ __forceinline__ unsigned long long ffma2(unsigned long long a,
                                                    unsigned long long b,
                                                    unsigned long long c) {
    unsigned long long d;
    asm("fma.rn.f32x2 %0, %1, %2, %3;" : "=l"(d) : "l"(a), "l"(b), "l"(c));
    return d;
}
__device__ __forceinline__ float psum(unsigned long long p) {
    float lo = __uint_as_float((unsigned int)(p & 0xFFFFFFFFull));
    float hi = __uint_as_float((unsigned int)(p >> 32));
    return lo + hi;
}

// ---------------- tf32 helpers ----------------
__device__ __forceinline__ float tf32_rna(float x) {
    float r;
    asm("cvt.rna.tf32.f32 %0, %1;" : "=f"(r) : "f"(x));
    return r;
}
__device__ __forceinline__ float2 split_tf32(float v) {
    const float hi = tf32_rna(v);
    const float lo = tf32_rna(v - hi);
    return make_float2(hi, lo);
}
__device__ __forceinline__ void mma_tf32_16x8x8(float* d, uint32_t a0, uint32_t a1,
                                                uint32_t a2, uint32_t a3,
                                                uint32_t b0, uint32_t b1) {
    asm volatile(
        "mma.sync.aligned.m16n8k8.row.col.f32.tf32.tf32.f32 "
        "{%0,%1,%2,%3}, {%4,%5,%6,%7}, {%8,%9}, {%0,%1,%2,%3};"
        : "+f"(d[0]), "+f"(d[1]), "+f"(d[2]), "+f"(d[3])
        : "r"(a0), "r"(a1), "r"(a2), "r"(a3), "r"(b0), "r"(b1));
}

// gemm smem: 2 bufs x (A:128x20 f2, B:128x20 f2) = 81920 B
#define GP 20                       // pitch in float2
#define GBUF (128 * GP)             // f2 per matrix per buf
#define GEMM_SMEM (2 * 2 * GBUF * 8)

// ---------------------------------------------------------------------------
// xw = x @ W^T + bW  via mma.sync tf32 3-term split.
// CTA 128x128, 8 warps (2m x 4n), warp tile 64x32 (4x4 m16n8 tiles), k16 chunks.
// ---------------------------------------------------------------------------
__global__ __launch_bounds__(256, 1)
void gemm_xw_mma(const float* __restrict__ X, const float* __restrict__ W,
                 const float* __restrict__ bW, float* __restrict__ C) {
    if (blockIdx.x == 0 && blockIdx.y == 0 && threadIdx.x < 4) {
        g_cnt4[threadIdx.x * 32] = 0;
        g_ack4[threadIdx.x * 32] = 0;
        g_flag4[threadIdx.x * 32] = 0;
    }

    extern __shared__ float2 gsm[];
    float2* As[2] = {gsm, gsm + 2 * GBUF};
    float2* Bs[2] = {gsm + GBUF, gsm + 3 * GBUF};

    const int tid = threadIdx.x;
    const int m0 = blockIdx.y * 128;
    const int n0 = blockIdx.x * 128;

    const int wid = tid >> 5;
    const int lane = tid & 31;
    const int wm = wid & 1;            // 2 m-groups
    const int wn = wid >> 1;           // 4 n-groups
    const int lr4 = lane >> 2;         // 0..7
    const int lc4 = lane & 3;          // 0..3
    const int awr = wm * 64;           // warp A row base (local)
    const int bwr = wn * 32;           // warp B row base (local)

    // fill mapping: two float4 rows per matrix per thread
    const int fr = tid >> 2;           // 0..63 (and +64)
    const int fc = (tid & 3) * 4;      // float col {0,4,8,12}
    const float* xg0 = X + (size_t)(m0 + fr) * II + fc;
    const float* xg1 = X + (size_t)(m0 + fr + 64) * II + fc;
    const float* wg0 = W + (size_t)(n0 + fr) * II + fc;
    const float* wg1 = W + (size_t)(n0 + fr + 64) * II + fc;

    float acc[4][4][4];
#pragma unroll
    for (int mt = 0; mt < 4; mt++)
#pragma unroll
        for (int nt = 0; nt < 4; nt++)
#pragma unroll
            for (int e = 0; e < 4; e++) acc[mt][nt][e] = 0.f;

    // helper lambda-ish macro: convert float4 -> 4 float2 and store
#define CVST(dst, roww, colw, v)                                              \
    do {                                                                      \
        float2 s_[4] = {split_tf32((v).x), split_tf32((v).y),                 \
                        split_tf32((v).z), split_tf32((v).w)};                \
        float2* dp_ = (dst) + (roww) * GP + (colw);                           \
        *(float4*)(dp_)     = *(float4*)&s_[0];                               \
        *(float4*)(dp_ + 2) = *(float4*)&s_[2];                               \
    } while (0)

    // preload chunk 0
    {
        const float4 a0 = *(const float4*)(xg0);
        const float4 a1 = *(const float4*)(xg1);
        const float4 b0 = *(const float4*)(wg0);
        const float4 b1 = *(const float4*)(wg1);
        CVST(As[0], fr, fc, a0);
        CVST(As[0], fr + 64, fc, a1);
        CVST(Bs[0], fr, fc, b0);
        CVST(Bs[0], fr + 64, fc, b1);
    }
    __syncthreads();

    int pb = 0;
    for (int k0 = 0; k0 < II; k0 += 16) {
        const bool more = (k0 + 16 < II);
        float4 nx0, nx1, nw0, nw1;
        if (more) {
            nx0 = *(const float4*)(xg0 + k0 + 16);
            nx1 = *(const float4*)(xg1 + k0 + 16);
            nw0 = *(const float4*)(wg0 + k0 + 16);
            nw1 = *(const float4*)(wg1 + k0 + 16);
        }
        const float2* Ap = As[pb];
        const float2* Bp = Bs[pb];
#pragma unroll
        for (int ko = 0; ko < 16; ko += 8) {
            // load fragments (packed hi/lo)
            float2 af[4][4];   // [mt][a0..a3]
            float2 bf[4][2];   // [nt][b0..b1]
#pragma unroll
            for (int mt = 0; mt < 4; mt++) {
                const int r = awr + mt * 16 + lr4;
                af[mt][0] = Ap[r * GP + ko + lc4];
                af[mt][1] = Ap[(r + 8) * GP + ko + lc4];
                af[mt][2] = Ap[r * GP + ko + 4 + lc4];
                af[mt][3] = Ap[(r + 8) * GP + ko + 4 + lc4];
            }
#pragma unroll
            for (int nt = 0; nt < 4; nt++) {
                const int r = bwr + nt * 8 + lr4;
                bf[nt][0] = Bp[r * GP + ko + lc4];
                bf[nt][1] = Bp[r * GP + ko + 4 + lc4];
            }
#pragma unroll
            for (int mt = 0; mt < 4; mt++) {
                const uint32_t ah0 = __float_as_uint(af[mt][0].x);
                const uint32_t ah1 = __float_as_uint(af[mt][1].x);
                const uint32_t ah2 = __float_as_uint(af[mt][2].x);
                const uint32_t ah3 = __float_as_uint(af[mt][3].x);
                const uint32_t al0 = __float_as_uint(af[mt][0].y);
                const uint32_t al1 = __float_as_uint(af[mt][1].y);
                const uint32_t al2 = __float_as_uint(af[mt][2].y);
                const uint32_t al3 = __float_as_uint(af[mt][3].y);
#pragma unroll
                for (int nt = 0; nt < 4; nt++) {
                    const uint32_t bh0 = __float_as_uint(bf[nt][0].x);
                    const uint32_t bh1 = __float_as_uint(bf[nt][1].x);
                    const uint32_t bl0 = __float_as_uint(bf[nt][0].y);
                    const uint32_t bl1 = __float_as_uint(bf[nt][1].y);
                    mma_tf32_16x8x8(acc[mt][nt], ah0, ah1, ah2, ah3, bh0, bh1);
                    mma_tf32_16x8x8(acc[mt][nt], ah0, ah1, ah2, ah3, bl0, bl1);
                    mma_tf32_16x8x8(acc[mt][nt], al0, al1, al2, al3, bh0, bh1);
                }
            }
        }
        if (more) {
            float2* An = As[pb ^ 1];
            float2* Bn = Bs[pb ^ 1];
            CVST(An, fr, fc, nx0);
            CVST(An, fr + 64, fc, nx1);
            CVST(Bn, fr, fc, nw0);
            CVST(Bn, fr + 64, fc, nw1);
        }
        __syncthreads();
        pb ^= 1;
    }
#undef CVST

    // epilogue: d0,d1 -> (row, 2c), (row, 2c+1); d2,d3 -> row+8
#pragma unroll
    for (int mt = 0; mt < 4; mt++) {
        const int row = m0 + wm * 64 + mt * 16 + lr4;
#pragma unroll
        for (int nt = 0; nt < 4; nt++) {
            const int col = n0 + wn * 32 + nt * 8 + 2 * lc4;
            const float2 bw = *(const float2*)(bW + col);
            float2 o0, o1;
            o0.x = acc[mt][nt][0] + bw.x;
            o0.y = acc[mt][nt][1] + bw.y;
            o1.x = acc[mt][nt][2] + bw.x;
            o1.y = acc[mt][nt][3] + bw.y;
            *(float2*)(C + (size_t)row * HH + col) = o0;
            *(float2*)(C + (size_t)(row + 8) * HH + col) = o1;
        }
    }
}

// ---------------------------------------------------------------------------
// Persistent recurrence (unchanged). 128 CTAs = 4(b) x 32(c) tiles of 16b x 32c.
// ---------------------------------------------------------------------------
__global__ __launch_bounds__(256, 1)
void rnn_steps_kernel(const float* __restrict__ U, const float* __restrict__ bU,
                      float* __restrict__ out) {
    extern __shared__ float fsmem[];
    float* Usm = fsmem;
    float* Hsm = fsmem + 32 * UPITCH;
    float* red = fsmem + 48 * UPITCH;

    const int tid = threadIdx.x;
    const int cgid = blockIdx.x & 31;
    const int bgid = blockIdx.x >> 5;
    const int c0 = cgid * 32;
    const int b0 = bgid * 16;
    const int bslot = bgid * 32;

    for (int idx = tid; idx < 32 * 1024; idx += 256) {
        const int r = idx >> 10, k = idx & 1023;
        Usm[r * UPITCH + k] = U[(size_t)(c0 + r) * HH + k];
    }

    const int o0 = 2 * tid;
    const int blo = o0 >> 5;
    const int clo = o0 & 31;
    const int b = b0 + blo;
    const int c = c0 + clo;
    const float bu0 = bU[c];
    const float bu1 = bU[c + 1];

    const int w = tid >> 5;
    const int lane = tid & 31;
    const int bg = lane & 3;
    const int cg = lane >> 2;
    const int kb1 = w * 64;
    const int kb2 = 512 + w * 64;

    const int sg = tid & 3;
    const int sk = tid >> 2;

    __syncthreads();

    {
        const size_t idx = ((size_t)b * TT) * HH + c;
        const float2 xw = *(const float2*)&out[idx];
        const float h0 = tanhf(xw.x);
        const float h1 = tanhf(xw.y);
        out[idx] = h0;
        out[idx + 1] = h1;
        g_h3[0][c][b] = h0;
        g_h3[0][c + 1][b] = h1;
    }
    __threadfence();
    __syncthreads();
    if (tid == 0) {
        if (atomicAdd(&g_cnt4[bslot], 1) == 31) {
            g_cnt4[bslot] = 0;
            __threadfence();
            g_flag4[bslot] = 1;
        } else {
            while (g_flag4[bslot] < 1u) { }
        }
    }
    __syncthreads();

    for (int t = 0; t < TT - 1; t++) {
        const int par = t & 1;
        const size_t nidx = ((size_t)b * TT + (t + 1)) * HH + c;
        const float2 xwn = *(const float2*)&out[nidx];
        const float* hb = &g_h3[par][0][0];

        {
            float4 v[8];
#pragma unroll
            for (int it = 0; it < 8; it++) {
                const int k = sk + 64 * it;
                v[it] = __ldcg((const float4*)(hb + (size_t)k * BB + b0 + 4 * sg));
            }
#pragma unroll
            for (int it = 0; it < 8; it++) {
                const int k = sk + 64 * it;
                float* dst = Hsm + k;
                dst[(4 * sg + 0) * UPITCH] = v[it].x;
                dst[(4 * sg + 1) * UPITCH] = v[it].y;
                dst[(4 * sg + 2) * UPITCH] = v[it].z;
                dst[(4 * sg + 3) * UPITCH] = v[it].w;
            }
        }
        __syncthreads();

        float4 v1[8];
#pragma unroll
        for (int it = 0; it < 8; it++) {
            const int k = 512 + sk + 64 * it;
            v1[it] = __ldcg((const float4*)(hb + (size_t)k * BB + b0 + 4 * sg));
        }

        unsigned long long acc[4][4];
#pragma unroll
        for (int i = 0; i < 4; i++)
#pragma unroll
            for (int q = 0; q < 4; q++) acc[i][q] = 0ull;

#pragma unroll 8
        for (int kp = 0; kp < 32; kp++) {
            const int k0 = kb1 + 2 * kp;
            unsigned long long a[4], u[4];
#pragma unroll
            for (int i = 0; i < 4; i++)
                a[i] = *(const unsigned long long*)&Hsm[(i * 4 + bg) * UPITCH + k0];
#pragma unroll
            for (int q = 0; q < 4; q++)
                u[q] = *(const unsigned long long*)&Usm[(q * 8 + cg) * UPITCH + k0];
#pragma unroll
            for (int i = 0; i < 4; i++)
#pragma unroll
                for (int q = 0; q < 4; q++)
                    acc[i][q] = ffma2(a[i], u[q], acc[i][q]);
        }

#pragma unroll
        for (int it = 0; it < 8; it++) {
            const int k = 512 + sk + 64 * it;
            float* dst = Hsm + k;
            dst[(4 * sg + 0) * UPITCH] = v1[it].x;
            dst[(4 * sg + 1) * UPITCH] = v1[it].y;
            dst[(4 * sg + 2) * UPITCH] = v1[it].z;
            dst[(4 * sg + 3) * UPITCH] = v1[it].w;
        }
        __syncthreads();

#pragma unroll 8
        for (int kp = 0; kp < 32; kp++) {
            const int k0 = kb2 + 2 * kp;
            unsigned long long a[4], u[4];
#pragma unroll
            for (int i = 0; i < 4; i++)
                a[i] = *(const unsigned long long*)&Hsm[(i * 4 + bg) * UPITCH + k0];
#pragma unroll
            for (int q = 0; q < 4; q++)
                u[q] = *(const unsigned long long*)&Usm[(q * 8 + cg) * UPITCH + k0];
#pragma unroll
            for (int i = 0; i < 4; i++)
#pragma unroll
                for (int q = 0; q < 4; q++)
                    acc[i][q] = ffma2(a[i], u[q], acc[i][q]);
        }

#pragma unroll
        for (int i = 0; i < 4; i++) {
            const int ob = (i * 4 + bg) * 32;
#pragma unroll
            for (int q = 0; q < 4; q++)
                red[w * 512 + ob + q * 8 + cg] = psum(acc[i][q]);
        }
        __syncthreads();

        float s0 = bu0, s1 = bu1;
#pragma unroll
        for (int ww = 0; ww < 8; ww++) {
            const float2 p = *(const float2*)&red[ww * 512 + o0];
            s0 += p.x;
            s1 += p.y;
        }

        const float h0 = tanhf(xwn.x + s0);
        const float h1 = tanhf(xwn.y + s1);
        out[nidx] = h0;
        out[nidx + 1] = h1;
        const int par1 = par ^ 1;
        g_h3[par1][c][b] = h0;
        g_h3[par1][c + 1][b] = h1;

        if (t == TT - 2) {
            const size_t o2 = (size_t)BB * TT * HH + (size_t)b * HH + c;
            out[o2] = h0;
            out[o2 + 1] = h1;
            break;
        }

        __threadfence();
        __syncthreads();
        if (tid == 0) {
            const unsigned int target = (unsigned int)(t + 2);
            if (atomicAdd(&g_cnt4[bslot], 1) == 31) {
                g_cnt4[bslot] = 0;
                __threadfence();
                g_flag4[bslot] = target;
            } else {
                while (g_flag4[bslot] < target) { }
            }
        }
        __syncthreads();
    }

    // replay-safe teardown
    __syncthreads();
    if (tid == 0) {
        const unsigned int target = (unsigned int)TT;
        if (atomicAdd(&g_cnt4[bslot], 1) == 31) {
            g_cnt4[bslot] = 0;
            __threadfence();
            g_flag4[bslot] = target;
        } else {
            while (g_flag4[bslot] < target) { }
        }
        if (atomicAdd(&g_ack4[bslot], 1) == 31) {
            g_ack4[bslot] = 0;
            g_flag4[bslot] = 0;
            __threadfence();
        }
    }
}

extern "C" void kernel_launch(void* const* d_in, const int* in_sizes, int n_in,
                              void* d_out, int out_size) {
    const float* x  = (const float*)d_in[0];
    const float* W  = (const float*)d_in[1];
    const float* bW = (const float*)d_in[2];
    const float* U  = (const float*)d_in[3];
    const float* bU = (const float*)d_in[4];
    float* out = (float*)d_out;

    cudaFuncSetAttribute(gemm_xw_mma,
                         cudaFuncAttributeMaxDynamicSharedMemorySize, GEMM_SMEM);
    const int rnn_smem = (48 * UPITCH + 8 * 512) * sizeof(float);
    cudaFuncSetAttribute(rnn_steps_kernel,
                         cudaFuncAttributeMaxDynamicSharedMemorySize, rnn_smem);

    dim3 ggrid(HH / 128, (BB * TT) / 128);  // (8, 256)
    gemm_xw_mma<<<ggrid, 256, GEMM_SMEM>>>(x, W, bW, out);

    rnn_steps_kernel<<<128, 256, rnn_smem>>>(U, bU, out);
}